// round 13
// baseline (speedup 1.0000x reference)
#include <cuda_runtime.h>
#include <cuda_bf16.h>
#include <math.h>
#include <stdint.h>

#define NN   20000
#define EE   320000
#define ET   (EE + NN)
#define FIN  745
#define K1P  768          // FIN padded to multiple of 32
#define HC1  1024         // 8 x 128
#define HC2  512          // 8 x 64
#define NCLS 10

// ==================== scratch (device globals) ====================
__device__ float d_h1[(size_t)NN * HC1];
__device__ float d_h2[(size_t)NN * HC2];
__device__ float d_g2[(size_t)NN * HC2];
__device__ float d_h3[(size_t)NN * NCLS];
__device__ float d_asrc[NN * 8];
__device__ float d_adst[NN * 8];
__device__ int   d_deg[NN];
__device__ int   d_rowptr[NN + 1];
__device__ int   d_cursor[NN];
__device__ int   d_esrc[ET];
// bf16 split buffers
__device__ __nv_bfloat16 d_xh[(size_t)NN * K1P];
__device__ __nv_bfloat16 d_xl[(size_t)NN * K1P];
__device__ __nv_bfloat16 d_w1h[(size_t)HC1 * K1P];
__device__ __nv_bfloat16 d_w1l[(size_t)HC1 * K1P];
__device__ __nv_bfloat16 d_w2h[(size_t)HC2 * HC1];
__device__ __nv_bfloat16 d_w2l[(size_t)HC2 * HC1];
__device__ __nv_bfloat16 d_g1h[(size_t)NN * HC1];
__device__ __nv_bfloat16 d_g1l[(size_t)NN * HC1];

#define BUF_H1 0
#define BUF_H2 1
#define BUF_G2 2
#define BUF_H3 3
__device__ __forceinline__ float* bufptr(int id) {
    switch (id) {
        case BUF_H1: return d_h1;
        case BUF_H2: return d_h2;
        case BUF_G2: return d_g2;
        default:     return d_h3;
    }
}
#define BF_XH 0
#define BF_XL 1
#define BF_W1H 2
#define BF_W1L 3
#define BF_W2H 4
#define BF_W2L 5
#define BF_G1H 6
#define BF_G1L 7
__device__ __forceinline__ __nv_bfloat16* bf16ptr(int id) {
    switch (id) {
        case BF_XH: return d_xh;
        case BF_XL: return d_xl;
        case BF_W1H: return d_w1h;
        case BF_W1L: return d_w1l;
        case BF_W2H: return d_w2h;
        case BF_W2L: return d_w2l;
        case BF_G1H: return d_g1h;
        default:     return d_g1l;
    }
}

// ==================== CSR build ====================
__global__ void k_count(const int* __restrict__ ei) {
    int e = blockIdx.x * blockDim.x + threadIdx.x;
    if (e >= ET) return;
    int dst = (e < EE) ? ei[EE + e] : (e - EE);
    if ((unsigned)dst < (unsigned)NN) atomicAdd(&d_deg[dst], 1);
}
__global__ void k_scan() {
    __shared__ int ssum[1024];
    const int CH = (NN + 1023) / 1024;
    int t = threadIdx.x, base = t * CH, s = 0;
    for (int i = 0; i < CH; i++) { int idx = base + i; if (idx < NN) s += d_deg[idx]; }
    ssum[t] = s;
    __syncthreads();
    for (int off = 1; off < 1024; off <<= 1) {
        int v = (t >= off) ? ssum[t - off] : 0;
        __syncthreads();
        ssum[t] += v;
        __syncthreads();
    }
    int run = ssum[t] - s;
    for (int i = 0; i < CH; i++) {
        int idx = base + i;
        if (idx < NN) { d_rowptr[idx] = run; d_cursor[idx] = run; run += d_deg[idx]; }
    }
    if (t == 1023) d_rowptr[NN] = ssum[1023];
}
__global__ void k_scatter(const int* __restrict__ ei) {
    int e = blockIdx.x * blockDim.x + threadIdx.x;
    if (e >= ET) return;
    int src, dst;
    if (e < EE) { src = ei[e]; dst = ei[EE + e]; }
    else        { src = dst = e - EE; }
    if ((unsigned)dst >= (unsigned)NN || (unsigned)src >= (unsigned)NN) return;
    int pos = atomicAdd(&d_cursor[dst], 1);
    d_esrc[pos] = src;
}

// ==================== fp32 -> bf16 hi/lo split (+optional aux zeroing) ===========
__global__ void k_split(const float* __restrict__ in, int rows, int Kin, int Kpad,
                        int hid, int lid, int zero_aux) {
    long long idx = (long long)blockIdx.x * blockDim.x + threadIdx.x;
    if (idx >= (long long)rows * Kpad) return;
    if (zero_aux) {
        if (idx < NN) d_deg[(int)idx] = 0;
        if (idx < NN * 8) { d_asrc[(int)idx] = 0.f; d_adst[(int)idx] = 0.f; }
    }
    int r = (int)(idx / Kpad), c = (int)(idx % Kpad);
    float v = (c < Kin) ? in[(size_t)r * Kin + c] : 0.f;
    __nv_bfloat16 hi = __float2bfloat16(v);
    bf16ptr(hid)[idx] = hi;
    bf16ptr(lid)[idx] = __float2bfloat16(v - __bfloat162float(hi));
}

__global__ void k_zero_att() {
    int i = blockIdx.x * blockDim.x + threadIdx.x;
    if (i < NN * 8) { d_asrc[i] = 0.f; d_adst[i] = 0.f; }
}

// ==================== pipelined mma.sync bf16-split GEMM + fused att ==========
// (unchanged from the 942us round-11 kernel)
#define PM 128
#define PN 64
#define PK 32
#define NSTAGE 2

__device__ __forceinline__ uint32_t swz64(int r, int c) {
    return (uint32_t)(r * 64 + ((c ^ ((r >> 1) & 3)) << 4));
}
__device__ __forceinline__ uint32_t smem_u32(const void* p) {
    uint32_t a;
    asm("{ .reg .u64 t; cvta.to.shared.u64 t, %1; cvt.u32.u64 %0, t; }" : "=r"(a) : "l"(p));
    return a;
}
__device__ __forceinline__ void cpa16(uint32_t s, const void* g, bool valid) {
    int sz = valid ? 16 : 0;
    asm volatile("cp.async.cg.shared.global [%0], [%1], 16, %2;" :: "r"(s), "l"(g), "r"(sz));
}
__device__ __forceinline__ void ldsm4(uint32_t* r, uint32_t addr) {
    asm volatile("ldmatrix.sync.aligned.m8n8.x4.shared.b16 {%0,%1,%2,%3}, [%4];"
        : "=r"(r[0]), "=r"(r[1]), "=r"(r[2]), "=r"(r[3]) : "r"(addr));
}
__device__ __forceinline__ void mma16816(float* d, const uint32_t* a, uint32_t b0, uint32_t b1) {
    asm volatile("mma.sync.aligned.m16n8k16.row.col.f32.bf16.bf16.f32 "
        "{%0,%1,%2,%3}, {%4,%5,%6,%7}, {%8,%9}, {%0,%1,%2,%3};"
        : "+f"(d[0]), "+f"(d[1]), "+f"(d[2]), "+f"(d[3])
        : "r"(a[0]), "r"(a[1]), "r"(a[2]), "r"(a[3]), "r"(b0), "r"(b1));
}

__global__ __launch_bounds__(256, 3) void k_mma(int ahid, int alid, int bhid, int blid,
                                                int cid, int M, int N, int K,
                                                const float* __restrict__ asv,
                                                const float* __restrict__ adv,
                                                int attC, int attH) {
    __shared__ __nv_bfloat16 sA[NSTAGE][2][PM * 32];
    __shared__ __nv_bfloat16 sB[NSTAGE][2][PN * 32];
    const __nv_bfloat16* __restrict__ Ah = bf16ptr(ahid);
    const __nv_bfloat16* __restrict__ Al = bf16ptr(alid);
    const __nv_bfloat16* __restrict__ Bh = bf16ptr(bhid);
    const __nv_bfloat16* __restrict__ Bl = bf16ptr(blid);
    float* __restrict__ C = bufptr(cid);

    int tid = threadIdx.x, warp = tid >> 5, lane = tid & 31;
    int wm = warp & 3, wn = warp >> 2;
    int row0 = blockIdx.y * PM, col0 = blockIdx.x * PN;

    int a_r = tid >> 2, a_c = tid & 3;
    int b_r = (tid >> 2) & 63, b_c = tid & 3;
    bool a_ok0 = (row0 + a_r) < M;
    bool a_ok1 = (row0 + a_r + 64) < M;
    size_t a_off0 = (size_t)(row0 + a_r) * K + a_c * 8;
    size_t a_off1 = (size_t)(row0 + a_r + 64) * K + a_c * 8;
    size_t b_off  = (size_t)(col0 + b_r) * K + b_c * 8;
    uint32_t aw0 = swz64(a_r, a_c), aw1 = swz64(a_r + 64, a_c), bw = swz64(b_r, b_c);
    uint32_t baseAh[2] = { smem_u32(&sA[0][0][0]), smem_u32(&sA[1][0][0]) };
    uint32_t baseAl[2] = { smem_u32(&sA[0][1][0]), smem_u32(&sA[1][1][0]) };
    uint32_t baseBh[2] = { smem_u32(&sB[0][0][0]), smem_u32(&sB[1][0][0]) };
    uint32_t baseBl[2] = { smem_u32(&sB[0][1][0]), smem_u32(&sB[1][1][0]) };

    float acc[2][4][4];
#pragma unroll
    for (int m = 0; m < 2; m++)
#pragma unroll
        for (int n = 0; n < 4; n++)
#pragma unroll
            for (int v = 0; v < 4; v++) acc[m][n][v] = 0.f;

    int lrow = lane & 15;
    int lck = lane >> 4;
    uint32_t offA[2][2], offB[2][2];
#pragma unroll
    for (int m = 0; m < 2; m++)
#pragma unroll
        for (int kk = 0; kk < 2; kk++) {
            offA[m][kk] = swz64(wm * 32 + m * 16 + lrow, 2 * kk + lck);
            offB[m][kk] = swz64(wn * 32 + m * 16 + lrow, 2 * kk + lck);
        }

    int nst = K / PK;
    {
        cpa16(baseAh[0] + aw0, Ah + a_off0, a_ok0);
        cpa16(baseAh[0] + aw1, Ah + a_off1, a_ok1);
        cpa16(baseAl[0] + aw0, Al + a_off0, a_ok0);
        cpa16(baseAl[0] + aw1, Al + a_off1, a_ok1);
        cpa16(baseBh[0] + bw, Bh + b_off, true);
        cpa16(baseBl[0] + bw, Bl + b_off, true);
        asm volatile("cp.async.commit_group;");
    }

    for (int s = 0; s < nst; s++) {
        int slot = s & 1;
        asm volatile("cp.async.wait_group 0;");
        __syncthreads();
        if (s + 1 < nst) {
            int wr = slot ^ 1;
            int kb = (s + 1) * PK;
            cpa16(baseAh[wr] + aw0, Ah + a_off0 + kb, a_ok0);
            cpa16(baseAh[wr] + aw1, Ah + a_off1 + kb, a_ok1);
            cpa16(baseAl[wr] + aw0, Al + a_off0 + kb, a_ok0);
            cpa16(baseAl[wr] + aw1, Al + a_off1 + kb, a_ok1);
            cpa16(baseBh[wr] + bw, Bh + b_off + kb, true);
            cpa16(baseBl[wr] + bw, Bl + b_off + kb, true);
            asm volatile("cp.async.commit_group;");
        }
#pragma unroll
        for (int kk = 0; kk < 2; kk++) {
            uint32_t ah[2][4], al[2][4], bh[2][4], bl[2][4];
            ldsm4(ah[0], baseAh[slot] + offA[0][kk]);
            ldsm4(ah[1], baseAh[slot] + offA[1][kk]);
            ldsm4(bh[0], baseBh[slot] + offB[0][kk]);
            ldsm4(bh[1], baseBh[slot] + offB[1][kk]);
            ldsm4(al[0], baseAl[slot] + offA[0][kk]);
            ldsm4(al[1], baseAl[slot] + offA[1][kk]);
#pragma unroll
            for (int m = 0; m < 2; m++)
#pragma unroll
                for (int j = 0; j < 2; j++)
#pragma unroll
                    for (int hf = 0; hf < 2; hf++)
                        mma16816(acc[m][j * 2 + hf], ah[m], bh[j][hf], bh[j][hf + 2]);
            ldsm4(bl[0], baseBl[slot] + offB[0][kk]);
            ldsm4(bl[1], baseBl[slot] + offB[1][kk]);
#pragma unroll
            for (int m = 0; m < 2; m++)
#pragma unroll
                for (int j = 0; j < 2; j++)
#pragma unroll
                    for (int hf = 0; hf < 2; hf++)
                        mma16816(acc[m][j * 2 + hf], al[m], bh[j][hf], bh[j][hf + 2]);
#pragma unroll
            for (int m = 0; m < 2; m++)
#pragma unroll
                for (int j = 0; j < 2; j++)
#pragma unroll
                    for (int hf = 0; hf < 2; hf++)
                        mma16816(acc[m][j * 2 + hf], ah[m], bl[j][hf], bl[j][hf + 2]);
        }
    }

#pragma unroll
    for (int m = 0; m < 2; m++) {
        int r0 = row0 + wm * 32 + m * 16 + (lane >> 2);
#pragma unroll
        for (int n8 = 0; n8 < 4; n8++) {
            int cc = col0 + wn * 32 + n8 * 8 + (lane & 3) * 2;
            if (r0 < M)
                *(float2*)&C[(size_t)r0 * N + cc] = make_float2(acc[m][n8][0], acc[m][n8][1]);
            if (r0 + 8 < M)
                *(float2*)&C[(size_t)(r0 + 8) * N + cc] = make_float2(acc[m][n8][2], acc[m][n8][3]);
        }
    }

    if (attC) {
        int h = col0 / attC;
        int cbase = col0 % attC;
        float ps[2][2], pd[2][2];
#pragma unroll
        for (int m = 0; m < 2; m++) { ps[m][0] = ps[m][1] = pd[m][0] = pd[m][1] = 0.f; }
#pragma unroll
        for (int n8 = 0; n8 < 4; n8++) {
            int cl = cbase + wn * 32 + n8 * 8 + (lane & 3) * 2;
            float a0 = asv[h * attC + cl], a1 = asv[h * attC + cl + 1];
            float e0 = adv[h * attC + cl], e1 = adv[h * attC + cl + 1];
#pragma unroll
            for (int m = 0; m < 2; m++) {
                ps[m][0] += a0 * acc[m][n8][0] + a1 * acc[m][n8][1];
                ps[m][1] += a0 * acc[m][n8][2] + a1 * acc[m][n8][3];
                pd[m][0] += e0 * acc[m][n8][0] + e1 * acc[m][n8][1];
                pd[m][1] += e0 * acc[m][n8][2] + e1 * acc[m][n8][3];
            }
        }
#pragma unroll
        for (int off = 1; off <= 2; off <<= 1) {
#pragma unroll
            for (int m = 0; m < 2; m++) {
                ps[m][0] += __shfl_xor_sync(0xffffffffu, ps[m][0], off);
                ps[m][1] += __shfl_xor_sync(0xffffffffu, ps[m][1], off);
                pd[m][0] += __shfl_xor_sync(0xffffffffu, pd[m][0], off);
                pd[m][1] += __shfl_xor_sync(0xffffffffu, pd[m][1], off);
            }
        }
        if ((lane & 3) == 0) {
#pragma unroll
            for (int m = 0; m < 2; m++)
#pragma unroll
                for (int hf = 0; hf < 2; hf++) {
                    int r = row0 + wm * 32 + m * 16 + (lane >> 2) + hf * 8;
                    if (r < M) {
                        atomicAdd(&d_asrc[r * attH + h], ps[m][hf]);
                        atomicAdd(&d_adst[r * attH + h], pd[m][hf]);
                    }
                }
        }
    }
}

// ==================== layer-3 skinny GEMM + fused attention coeffs ====================
__global__ __launch_bounds__(256) void k_gemm3(const float* __restrict__ W3,
                                               const float* __restrict__ as3,
                                               const float* __restrict__ ad3) {
    __shared__ float sW[NCLS * HC2];
    __shared__ float sas[NCLS], sad[NCLS];
    int tid = threadIdx.x;
    for (int i = tid; i < NCLS * HC2; i += 256) sW[i] = W3[i];
    if (tid < NCLS) { sas[tid] = as3[tid]; sad[tid] = ad3[tid]; }
    __syncthreads();
    int warp = tid >> 5, lane = tid & 31;
    int r = blockIdx.x * 8 + warp;
    if (r >= NN) return;
    const float4* g = (const float4*)(d_g2 + (size_t)r * HC2);
    float pc[NCLS];
#pragma unroll
    for (int c = 0; c < NCLS; c++) pc[c] = 0.f;
#pragma unroll
    for (int i = 0; i < 4; i++) {
        float4 v = g[lane + i * 32];
        int k = (lane + i * 32) * 4;
#pragma unroll
        for (int c = 0; c < NCLS; c++) {
            float4 w = *(const float4*)&sW[c * HC2 + k];
            pc[c] += v.x * w.x + v.y * w.y + v.z * w.z + v.w * w.w;
        }
    }
    float s1 = 0.f, s2 = 0.f;
#pragma unroll
    for (int c = 0; c < NCLS; c++) {
        float t = pc[c];
#pragma unroll
        for (int o = 16; o; o >>= 1) t += __shfl_xor_sync(0xffffffffu, t, o);
        if (lane == c) d_h3[(size_t)r * NCLS + c] = t;
        s1 += t * sas[c];
        s2 += t * sad[c];
    }
    if (lane == 0) { d_asrc[r] = s1; d_adst[r] = s2; }
}

// ==================== single-pass segment softmax + aggregate (MLP-4 gather) ===
template <int H, int C, int V, bool RELU, int OMODE>   // OMODE 0: fp32; 1: bf16 hi/lo split
__global__ __launch_bounds__(256) void k_agg(int Hid, const float* __restrict__ bias,
                                             int Oid, int OhId, int OlId) {
    constexpr int HC = H * C;
    const float* __restrict__ hin = bufptr(Hid);
    int n = blockIdx.x, tid = threadIdx.x;
    int row = d_rowptr[n], cnt = d_rowptr[n + 1] - row;

    __shared__ float s_adst[H];
    __shared__ float s_w[H * 128];
    __shared__ int   s_src[128];
    __shared__ float s_inv[H];

    if (tid < H) s_adst[tid] = d_adst[n * H + tid];
    __syncthreads();

    int cb = tid * V;
    bool act = cb < HC;
    int head = act ? cb / C : 0;
    bool sumth = act && ((cb % C) == 0);
    float acc[V];
#pragma unroll
    for (int v = 0; v < V; v++) acc[v] = 0.f;
    float swacc = 0.f;

    for (int c0 = 0; c0 < cnt; c0 += 128) {
        int cl = min(128, cnt - c0);
        __syncthreads();
        if (tid < cl) {
            int s = d_esrc[row + c0 + tid];
            s_src[tid] = s;
#pragma unroll
            for (int h = 0; h < H; h++) {
                float e = d_asrc[s * H + h] + s_adst[h];
                e = e > 0.f ? e : 0.2f * e;
                s_w[h * 128 + tid] = __expf(e);
            }
        }
        __syncthreads();
        if (act) {
            const float* wrow = &s_w[head * 128];
            int j = 0;
            for (; j + 4 <= cl; j += 4) {
                int s0 = s_src[j], s1 = s_src[j + 1], s2 = s_src[j + 2], s3 = s_src[j + 3];
                float w0 = wrow[j], w1 = wrow[j + 1], w2 = wrow[j + 2], w3 = wrow[j + 3];
                if (V == 4) {
                    float4 t0 = *(const float4*)(hin + (size_t)s0 * HC + cb);
                    float4 t1 = *(const float4*)(hin + (size_t)s1 * HC + cb);
                    float4 t2 = *(const float4*)(hin + (size_t)s2 * HC + cb);
                    float4 t3 = *(const float4*)(hin + (size_t)s3 * HC + cb);
                    acc[0] += w0 * t0.x; acc[1] += w0 * t0.y; acc[2] += w0 * t0.z; acc[3] += w0 * t0.w;
                    acc[0] += w1 * t1.x; acc[1] += w1 * t1.y; acc[2] += w1 * t1.z; acc[3] += w1 * t1.w;
                    acc[0] += w2 * t2.x; acc[1] += w2 * t2.y; acc[2] += w2 * t2.z; acc[3] += w2 * t2.w;
                    acc[0] += w3 * t3.x; acc[1] += w3 * t3.y; acc[2] += w3 * t3.z; acc[3] += w3 * t3.w;
                } else if (V == 2) {
                    float2 t0 = *(const float2*)(hin + (size_t)s0 * HC + cb);
                    float2 t1 = *(const float2*)(hin + (size_t)s1 * HC + cb);
                    float2 t2 = *(const float2*)(hin + (size_t)s2 * HC + cb);
                    float2 t3 = *(const float2*)(hin + (size_t)s3 * HC + cb);
                    acc[0] += w0 * t0.x; acc[1] += w0 * t0.y;
                    acc[0] += w1 * t1.x; acc[1] += w1 * t1.y;
                    acc[0] += w2 * t2.x; acc[1] += w2 * t2.y;
                    acc[0] += w3 * t3.x; acc[1] += w3 * t3.y;
                } else {
                    float t0 = hin[(size_t)s0 * HC + cb];
                    float t1 = hin[(size_t)s1 * HC + cb];
                    float t2 = hin[(size_t)s2 * HC + cb];
                    float t3 = hin[(size_t)s3 * HC + cb];
                    acc[0] += w0 * t0; acc[0] += w1 * t1; acc[0] += w2 * t2; acc[0] += w3 * t3;
                }
                if (sumth) { swacc += w0; swacc += w1; swacc += w2; swacc += w3; }
            }
            for (; j < cl; j++) {
                int s = s_src[j];
                float w = wrow[j];
                const float* hp = hin + (size_t)s * HC + cb;
                if (V == 4) {
                    float4 t = *(const float4*)hp;
                    acc[0] += w * t.x; acc[1] += w * t.y;
                    acc[2] += w * t.z; acc[3] += w * t.w;
                } else if (V == 2) {
                    float2 t = *(const float2*)hp;
                    acc[0] += w * t.x; acc[1] += w * t.y;
                } else {
                    acc[0] += w * hp[0];
                }
                if (sumth) swacc += w;
            }
        }
    }
    if (sumth) s_inv[head] = 1.f / (swacc + 1e-16f);
    __syncthreads();
    if (act) {
        float inv = s_inv[head];
#pragma unroll
        for (int v = 0; v < V; v++) {
            float val = acc[v] * inv + bias[cb + v];
            if (RELU) val = fmaxf(val, 0.f);
            if (OMODE == 0) {
                bufptr(Oid)[(size_t)n * HC + cb + v] = val;
            } else {
                __nv_bfloat16 hi = __float2bfloat16(val);
                bf16ptr(OhId)[(size_t)n * HC + cb + v] = hi;
                bf16ptr(OlId)[(size_t)n * HC + cb + v] = __float2bfloat16(val - __bfloat162float(hi));
            }
        }
    }
}

// ==================== layer-3 aggregate + log_softmax (warp per node) =========
__global__ __launch_bounds__(256) void k_agg3lsm(const float* __restrict__ b3,
                                                 float* __restrict__ out) {
    int warp = threadIdx.x >> 5, lane = threadIdx.x & 31;
    int n = blockIdx.x * 8 + warp;
    if (n >= NN) return;
    int row = d_rowptr[n];
    int cnt = d_rowptr[n + 1] - row;
    float adst = d_adst[n];
    bool actc = lane < NCLS;
    float acc = 0.f, swacc = 0.f;
    int j = 0;
    for (; j + 2 <= cnt; j += 2) {
        int s0 = d_esrc[row + j], s1 = d_esrc[row + j + 1];
        float e0 = d_asrc[s0] + adst, e1 = d_asrc[s1] + adst;
        e0 = e0 > 0.f ? e0 : 0.2f * e0;
        e1 = e1 > 0.f ? e1 : 0.2f * e1;
        float w0 = __expf(e0), w1 = __expf(e1);
        float t0 = actc ? d_h3[(size_t)s0 * NCLS + lane] : 0.f;
        float t1 = actc ? d_h3[(size_t)s1 * NCLS + lane] : 0.f;
        acc += w0 * t0; acc += w1 * t1;
        swacc += w0; swacc += w1;
    }
    for (; j < cnt; j++) {
        int s = d_esrc[row + j];
        float e = d_asrc[s] + adst;
        e = e > 0.f ? e : 0.2f * e;
        float w = __expf(e);
        if (actc) acc += w * d_h3[(size_t)s * NCLS + lane];
        swacc += w;
    }
    float inv = 1.f / (swacc + 1e-16f);
    float val = actc ? (acc * inv + b3[lane]) : -1e30f;
    // log_softmax over the 10 channels (16-lane shfl tree; lanes 10-15 padded)
    float m = val;
#pragma unroll
    for (int o = 8; o; o >>= 1) m = fmaxf(m, __shfl_xor_sync(0xffffffffu, m, o));
    float ex = actc ? __expf(val - m) : 0.f;
    float ssum = ex;
#pragma unroll
    for (int o = 8; o; o >>= 1) ssum += __shfl_xor_sync(0xffffffffu, ssum, o);
    if (actc) out[n * NCLS + lane] = val - (m + logf(ssum));
}

// ==================== launch ====================
extern "C" void kernel_launch(void* const* d_in, const int* in_sizes, int n_in,
                              void* d_out, int out_size) {
    const float* x   = (const float*)d_in[0];
    const int*   ei  = (const int*)d_in[1];
    const float* W1  = (const float*)d_in[2];
    const float* as1 = (const float*)d_in[3];
    const float* ad1 = (const float*)d_in[4];
    const float* b1  = (const float*)d_in[5];
    const float* W2  = (const float*)d_in[6];
    const float* as2 = (const float*)d_in[7];
    const float* ad2 = (const float*)d_in[8];
    const float* b2  = (const float*)d_in[9];
    const float* W3  = (const float*)d_in[10];
    const float* as3 = (const float*)d_in[11];
    const float* ad3 = (const float*)d_in[12];
    const float* b3  = (const float*)d_in[13];
    float* out = (float*)d_out;

    // 0-2: bf16 splits (split_x also zeroes deg/asrc/adst)
    k_split<<<(int)(((long long)NN * K1P + 255) / 256), 256>>>(x, NN, FIN, K1P, BF_XH, BF_XL, 1);
    k_split<<<(HC1 * K1P + 255) / 256, 256>>>(W1, HC1, FIN, K1P, BF_W1H, BF_W1L, 0);
    k_split<<<(HC2 * HC1 + 255) / 256, 256>>>(W2, HC2, HC1, HC1, BF_W2H, BF_W2L, 0);

    // 3: layer-1 GEMM + fused att coeffs  (ncu -s 5 captures this launch)
    {
        dim3 grid(HC1 / PN, (NN + PM - 1) / PM);
        k_mma<<<grid, 256>>>(BF_XH, BF_XL, BF_W1H, BF_W1L, BUF_H1, NN, HC1, K1P,
                             as1, ad1, 128, 8);
    }

    // 4-6: CSR build
    k_count<<<(ET + 255) / 256, 256>>>(ei);
    k_scan<<<1, 1024>>>();
    k_scatter<<<(ET + 255) / 256, 256>>>(ei);

    // 7: layer-1 aggregate -> g1 (bf16 split)
    k_agg<8, 128, 4, true, 1><<<NN, 256>>>(BUF_H1, b1, 0, BF_G1H, BF_G1L);

    // 8: re-zero att accumulators for layer 2
    k_zero_att<<<(NN * 8 + 255) / 256, 256>>>();

    // 9-10: layer 2
    {
        dim3 grid(HC2 / PN, (NN + PM - 1) / PM);
        k_mma<<<grid, 256>>>(BF_G1H, BF_G1L, BF_W2H, BF_W2L, BUF_H2, NN, HC2, HC1,
                             as2, ad2, 64, 8);
        k_agg<8, 64, 2, true, 0><<<NN, 256>>>(BUF_H2, b2, BUF_G2, 0, 0);
    }
    // 11-12: layer 3 (fused agg + log_softmax)
    {
        k_gemm3<<<(NN + 7) / 8, 256>>>(W3, as3, ad3);
        k_agg3lsm<<<(NN + 7) / 8, 256>>>(b3, out);
    }
}

// round 14
// speedup vs baseline: 1.5769x; 1.5769x over previous
#include <cuda_runtime.h>
#include <cuda_fp16.h>
#include <math.h>
#include <stdint.h>

#define NN   20000
#define EE   320000
#define ET   (EE + NN)
#define FIN  745
#define K1P  768          // FIN padded to multiple of 32
#define HC1  1024         // 8 x 128
#define HC2  512          // 8 x 64
#define NCLS 10

// ==================== scratch (device globals) ====================
__device__ float d_h1[(size_t)NN * HC1];
__device__ float d_h2[(size_t)NN * HC2];
__device__ float d_g2[(size_t)NN * HC2];
__device__ float d_h3[(size_t)NN * NCLS];
__device__ float d_asrc[NN * 8];
__device__ float d_adst[NN * 8];
__device__ int   d_deg[NN];
__device__ int   d_rowptr[NN + 1];
__device__ int   d_cursor[NN];
__device__ int   d_esrc[ET];
// fp16 operand buffers
__device__ __half d_xh[(size_t)NN * K1P];
__device__ __half d_w1h[(size_t)HC1 * K1P];
__device__ __half d_w2h[(size_t)HC2 * HC1];
__device__ __half d_g1h[(size_t)NN * HC1];

#define BUF_H1 0
#define BUF_H2 1
#define BUF_G2 2
#define BUF_H3 3
__device__ __forceinline__ float* bufptr(int id) {
    switch (id) {
        case BUF_H1: return d_h1;
        case BUF_H2: return d_h2;
        case BUF_G2: return d_g2;
        default:     return d_h3;
    }
}
#define HF_XH  0
#define HF_W1H 1
#define HF_W2H 2
#define HF_G1H 3
__device__ __forceinline__ __half* halfptr(int id) {
    switch (id) {
        case HF_XH:  return d_xh;
        case HF_W1H: return d_w1h;
        case HF_W2H: return d_w2h;
        default:     return d_g1h;
    }
}

// ==================== CSR build ====================
__global__ void k_count(const int* __restrict__ ei) {
    int e = blockIdx.x * blockDim.x + threadIdx.x;
    if (e >= ET) return;
    int dst = (e < EE) ? ei[EE + e] : (e - EE);
    if ((unsigned)dst < (unsigned)NN) atomicAdd(&d_deg[dst], 1);
}
__global__ void k_scan() {
    __shared__ int ssum[1024];
    const int CH = (NN + 1023) / 1024;
    int t = threadIdx.x, base = t * CH, s = 0;
    for (int i = 0; i < CH; i++) { int idx = base + i; if (idx < NN) s += d_deg[idx]; }
    ssum[t] = s;
    __syncthreads();
    for (int off = 1; off < 1024; off <<= 1) {
        int v = (t >= off) ? ssum[t - off] : 0;
        __syncthreads();
        ssum[t] += v;
        __syncthreads();
    }
    int run = ssum[t] - s;
    for (int i = 0; i < CH; i++) {
        int idx = base + i;
        if (idx < NN) { d_rowptr[idx] = run; d_cursor[idx] = run; run += d_deg[idx]; }
    }
    if (t == 1023) d_rowptr[NN] = ssum[1023];
}
__global__ void k_scatter(const int* __restrict__ ei) {
    int e = blockIdx.x * blockDim.x + threadIdx.x;
    if (e >= ET) return;
    int src, dst;
    if (e < EE) { src = ei[e]; dst = ei[EE + e]; }
    else        { src = dst = e - EE; }
    if ((unsigned)dst >= (unsigned)NN || (unsigned)src >= (unsigned)NN) return;
    int pos = atomicAdd(&d_cursor[dst], 1);
    d_esrc[pos] = src;
}

// ==================== fp32 -> fp16 convert (+optional aux zeroing) ============
__global__ void k_half(const float* __restrict__ in, int rows, int Kin, int Kpad,
                       int hid, int zero_aux) {
    long long idx = (long long)blockIdx.x * blockDim.x + threadIdx.x;
    if (idx >= (long long)rows * Kpad) return;
    if (zero_aux) {
        if (idx < NN) d_deg[(int)idx] = 0;
        if (idx < NN * 8) { d_asrc[(int)idx] = 0.f; d_adst[(int)idx] = 0.f; }
    }
    int r = (int)(idx / Kpad), c = (int)(idx % Kpad);
    float v = (c < Kin) ? in[(size_t)r * Kin + c] : 0.f;
    halfptr(hid)[idx] = __float2half_rn(v);
}

__global__ void k_zero_att() {
    int i = blockIdx.x * blockDim.x + threadIdx.x;
    if (i < NN * 8) { d_asrc[i] = 0.f; d_adst[i] = 0.f; }
}

// ==================== pipelined mma.sync fp16 GEMM + fused att ================
// C[M,N] = A[M,K] @ B[N,K]^T ;  BM=128, BN=64, BK=32, 2-slot double buffer
// SMEM: 64B rows, XOR-swizzled 16B chunks: pc = ck ^ ((r>>1)&3)
#define PM 128
#define PN 64
#define PK 32
#define NSTAGE 2

__device__ __forceinline__ uint32_t swz64(int r, int c) {
    return (uint32_t)(r * 64 + ((c ^ ((r >> 1) & 3)) << 4));
}
__device__ __forceinline__ uint32_t smem_u32(const void* p) {
    uint32_t a;
    asm("{ .reg .u64 t; cvta.to.shared.u64 t, %1; cvt.u32.u64 %0, t; }" : "=r"(a) : "l"(p));
    return a;
}
__device__ __forceinline__ void cpa16(uint32_t s, const void* g, bool valid) {
    int sz = valid ? 16 : 0;
    asm volatile("cp.async.cg.shared.global [%0], [%1], 16, %2;" :: "r"(s), "l"(g), "r"(sz));
}
__device__ __forceinline__ void ldsm4(uint32_t* r, uint32_t addr) {
    asm volatile("ldmatrix.sync.aligned.m8n8.x4.shared.b16 {%0,%1,%2,%3}, [%4];"
        : "=r"(r[0]), "=r"(r[1]), "=r"(r[2]), "=r"(r[3]) : "r"(addr));
}
__device__ __forceinline__ void mma16816(float* d, const uint32_t* a, uint32_t b0, uint32_t b1) {
    asm volatile("mma.sync.aligned.m16n8k16.row.col.f32.f16.f16.f32 "
        "{%0,%1,%2,%3}, {%4,%5,%6,%7}, {%8,%9}, {%0,%1,%2,%3};"
        : "+f"(d[0]), "+f"(d[1]), "+f"(d[2]), "+f"(d[3])
        : "r"(a[0]), "r"(a[1]), "r"(a[2]), "r"(a[3]), "r"(b0), "r"(b1));
}

__global__ __launch_bounds__(256, 3) void k_mma(int ahid, int bhid,
                                                int cid, int M, int N, int K,
                                                const float* __restrict__ asv,
                                                const float* __restrict__ adv,
                                                int attC, int attH) {
    __shared__ __half sA[NSTAGE][PM * 32];   // 2 x 8KB
    __shared__ __half sB[NSTAGE][PN * 32];   // 2 x 4KB
    const __half* __restrict__ Ah = halfptr(ahid);
    const __half* __restrict__ Bh = halfptr(bhid);
    float* __restrict__ C = bufptr(cid);

    int tid = threadIdx.x, warp = tid >> 5, lane = tid & 31;
    int wm = warp & 3, wn = warp >> 2;              // 4x2 warps, warp tile 32x32
    int row0 = blockIdx.y * PM, col0 = blockIdx.x * PN;

    // load-thread mapping: A 128x4 chunks (rows r, r+64), B 64x4 chunks
    int a_r = tid >> 2, a_c = tid & 3;
    int b_r = (tid >> 2) & 63, b_c = tid & 3;
    bool a_ok0 = (row0 + a_r) < M;
    bool a_ok1 = (row0 + a_r + 64) < M;
    size_t a_off0 = (size_t)(row0 + a_r) * K + a_c * 8;
    size_t a_off1 = (size_t)(row0 + a_r + 64) * K + a_c * 8;
    size_t b_off  = (size_t)(col0 + b_r) * K + b_c * 8;
    uint32_t aw0 = swz64(a_r, a_c), aw1 = swz64(a_r + 64, a_c), bw = swz64(b_r, b_c);
    uint32_t baseA[2] = { smem_u32(&sA[0][0]), smem_u32(&sA[1][0]) };
    uint32_t baseB[2] = { smem_u32(&sB[0][0]), smem_u32(&sB[1][0]) };

    float acc[2][4][4];
#pragma unroll
    for (int m = 0; m < 2; m++)
#pragma unroll
        for (int n = 0; n < 4; n++)
#pragma unroll
            for (int v = 0; v < 4; v++) acc[m][n][v] = 0.f;

    int lrow = lane & 15;
    int lck = lane >> 4;
    uint32_t offA[2][2], offB[2][2];
#pragma unroll
    for (int m = 0; m < 2; m++)
#pragma unroll
        for (int kk = 0; kk < 2; kk++) {
            offA[m][kk] = swz64(wm * 32 + m * 16 + lrow, 2 * kk + lck);
            offB[m][kk] = swz64(wn * 32 + m * 16 + lrow, 2 * kk + lck);
        }

    int nst = K / PK;
    // prologue
    {
        cpa16(baseA[0] + aw0, Ah + a_off0, a_ok0);
        cpa16(baseA[0] + aw1, Ah + a_off1, a_ok1);
        cpa16(baseB[0] + bw, Bh + b_off, true);
        asm volatile("cp.async.commit_group;");
    }

    for (int s = 0; s < nst; s++) {
        int slot = s & 1;
        asm volatile("cp.async.wait_group 0;");
        __syncthreads();
        if (s + 1 < nst) {
            int wr = slot ^ 1;
            int kb = (s + 1) * PK;
            cpa16(baseA[wr] + aw0, Ah + a_off0 + kb, a_ok0);
            cpa16(baseA[wr] + aw1, Ah + a_off1 + kb, a_ok1);
            cpa16(baseB[wr] + bw, Bh + b_off + kb, true);
            asm volatile("cp.async.commit_group;");
        }
#pragma unroll
        for (int kk = 0; kk < 2; kk++) {
            uint32_t ah[2][4], bh[2][4];
            ldsm4(ah[0], baseA[slot] + offA[0][kk]);
            ldsm4(ah[1], baseA[slot] + offA[1][kk]);
            ldsm4(bh[0], baseB[slot] + offB[0][kk]);
            ldsm4(bh[1], baseB[slot] + offB[1][kk]);
#pragma unroll
            for (int m = 0; m < 2; m++)
#pragma unroll
                for (int j = 0; j < 2; j++)
#pragma unroll
                    for (int hf = 0; hf < 2; hf++)
                        mma16816(acc[m][j * 2 + hf], ah[m], bh[j][hf], bh[j][hf + 2]);
        }
    }

    // epilogue: store C
#pragma unroll
    for (int m = 0; m < 2; m++) {
        int r0 = row0 + wm * 32 + m * 16 + (lane >> 2);
#pragma unroll
        for (int n8 = 0; n8 < 4; n8++) {
            int cc = col0 + wn * 32 + n8 * 8 + (lane & 3) * 2;
            if (r0 < M)
                *(float2*)&C[(size_t)r0 * N + cc] = make_float2(acc[m][n8][0], acc[m][n8][1]);
            if (r0 + 8 < M)
                *(float2*)&C[(size_t)(r0 + 8) * N + cc] = make_float2(acc[m][n8][2], acc[m][n8][3]);
        }
    }

    // fused attention coefficients: one head per block
    if (attC) {
        int h = col0 / attC;
        int cbase = col0 % attC;
        float ps[2][2], pd[2][2];
#pragma unroll
        for (int m = 0; m < 2; m++) { ps[m][0] = ps[m][1] = pd[m][0] = pd[m][1] = 0.f; }
#pragma unroll
        for (int n8 = 0; n8 < 4; n8++) {
            int cl = cbase + wn * 32 + n8 * 8 + (lane & 3) * 2;
            float a0 = asv[h * attC + cl], a1 = asv[h * attC + cl + 1];
            float e0 = adv[h * attC + cl], e1 = adv[h * attC + cl + 1];
#pragma unroll
            for (int m = 0; m < 2; m++) {
                ps[m][0] += a0 * acc[m][n8][0] + a1 * acc[m][n8][1];
                ps[m][1] += a0 * acc[m][n8][2] + a1 * acc[m][n8][3];
                pd[m][0] += e0 * acc[m][n8][0] + e1 * acc[m][n8][1];
                pd[m][1] += e0 * acc[m][n8][2] + e1 * acc[m][n8][3];
            }
        }
#pragma unroll
        for (int off = 1; off <= 2; off <<= 1) {
#pragma unroll
            for (int m = 0; m < 2; m++) {
                ps[m][0] += __shfl_xor_sync(0xffffffffu, ps[m][0], off);
                ps[m][1] += __shfl_xor_sync(0xffffffffu, ps[m][1], off);
                pd[m][0] += __shfl_xor_sync(0xffffffffu, pd[m][0], off);
                pd[m][1] += __shfl_xor_sync(0xffffffffu, pd[m][1], off);
            }
        }
        if ((lane & 3) == 0) {
#pragma unroll
            for (int m = 0; m < 2; m++)
#pragma unroll
                for (int hf = 0; hf < 2; hf++) {
                    int r = row0 + wm * 32 + m * 16 + (lane >> 2) + hf * 8;
                    if (r < M) {
                        atomicAdd(&d_asrc[r * attH + h], ps[m][hf]);
                        atomicAdd(&d_adst[r * attH + h], pd[m][hf]);
                    }
                }
        }
    }
}

// ==================== layer-3 skinny GEMM + fused attention coeffs ====================
__global__ __launch_bounds__(256) void k_gemm3(const float* __restrict__ W3,
                                               const float* __restrict__ as3,
                                               const float* __restrict__ ad3) {
    __shared__ float sW[NCLS * HC2];
    __shared__ float sas[NCLS], sad[NCLS];
    int tid = threadIdx.x;
    for (int i = tid; i < NCLS * HC2; i += 256) sW[i] = W3[i];
    if (tid < NCLS) { sas[tid] = as3[tid]; sad[tid] = ad3[tid]; }
    __syncthreads();
    int warp = tid >> 5, lane = tid & 31;
    int r = blockIdx.x * 8 + warp;
    if (r >= NN) return;
    const float4* g = (const float4*)(d_g2 + (size_t)r * HC2);
    float pc[NCLS];
#pragma unroll
    for (int c = 0; c < NCLS; c++) pc[c] = 0.f;
#pragma unroll
    for (int i = 0; i < 4; i++) {
        float4 v = g[lane + i * 32];
        int k = (lane + i * 32) * 4;
#pragma unroll
        for (int c = 0; c < NCLS; c++) {
            float4 w = *(const float4*)&sW[c * HC2 + k];
            pc[c] += v.x * w.x + v.y * w.y + v.z * w.z + v.w * w.w;
        }
    }
    float s1 = 0.f, s2 = 0.f;
#pragma unroll
    for (int c = 0; c < NCLS; c++) {
        float t = pc[c];
#pragma unroll
        for (int o = 16; o; o >>= 1) t += __shfl_xor_sync(0xffffffffu, t, o);
        if (lane == c) d_h3[(size_t)r * NCLS + c] = t;
        s1 += t * sas[c];
        s2 += t * sad[c];
    }
    if (lane == 0) { d_asrc[r] = s1; d_adst[r] = s2; }
}

// ==================== single-pass segment softmax + aggregate (MLP-4 gather) ===
template <int H, int C, int V, bool RELU, int OMODE>   // OMODE 0: fp32; 1: fp16 out
__global__ __launch_bounds__(256) void k_agg(int Hid, const float* __restrict__ bias,
                                             int Oid, int OhId) {
    constexpr int HC = H * C;
    const float* __restrict__ hin = bufptr(Hid);
    int n = blockIdx.x, tid = threadIdx.x;
    int row = d_rowptr[n], cnt = d_rowptr[n + 1] - row;

    __shared__ float s_adst[H];
    __shared__ float s_w[H * 128];
    __shared__ int   s_src[128];
    __shared__ float s_inv[H];

    if (tid < H) s_adst[tid] = d_adst[n * H + tid];
    __syncthreads();

    int cb = tid * V;
    bool act = cb < HC;
    int head = act ? cb / C : 0;
    bool sumth = act && ((cb % C) == 0);
    float acc[V];
#pragma unroll
    for (int v = 0; v < V; v++) acc[v] = 0.f;
    float swacc = 0.f;

    for (int c0 = 0; c0 < cnt; c0 += 128) {
        int cl = min(128, cnt - c0);
        __syncthreads();
        if (tid < cl) {
            int s = d_esrc[row + c0 + tid];
            s_src[tid] = s;
#pragma unroll
            for (int h = 0; h < H; h++) {
                float e = d_asrc[s * H + h] + s_adst[h];
                e = e > 0.f ? e : 0.2f * e;
                s_w[h * 128 + tid] = __expf(e);
            }
        }
        __syncthreads();
        if (act) {
            const float* wrow = &s_w[head * 128];
            int j = 0;
            for (; j + 4 <= cl; j += 4) {
                int s0 = s_src[j], s1 = s_src[j + 1], s2 = s_src[j + 2], s3 = s_src[j + 3];
                float w0 = wrow[j], w1 = wrow[j + 1], w2 = wrow[j + 2], w3 = wrow[j + 3];
                if (V == 4) {
                    float4 t0 = *(const float4*)(hin + (size_t)s0 * HC + cb);
                    float4 t1 = *(const float4*)(hin + (size_t)s1 * HC + cb);
                    float4 t2 = *(const float4*)(hin + (size_t)s2 * HC + cb);
                    float4 t3 = *(const float4*)(hin + (size_t)s3 * HC + cb);
                    acc[0] += w0 * t0.x; acc[1] += w0 * t0.y; acc[2] += w0 * t0.z; acc[3] += w0 * t0.w;
                    acc[0] += w1 * t1.x; acc[1] += w1 * t1.y; acc[2] += w1 * t1.z; acc[3] += w1 * t1.w;
                    acc[0] += w2 * t2.x; acc[1] += w2 * t2.y; acc[2] += w2 * t2.z; acc[3] += w2 * t2.w;
                    acc[0] += w3 * t3.x; acc[1] += w3 * t3.y; acc[2] += w3 * t3.z; acc[3] += w3 * t3.w;
                } else if (V == 2) {
                    float2 t0 = *(const float2*)(hin + (size_t)s0 * HC + cb);
                    float2 t1 = *(const float2*)(hin + (size_t)s1 * HC + cb);
                    float2 t2 = *(const float2*)(hin + (size_t)s2 * HC + cb);
                    float2 t3 = *(const float2*)(hin + (size_t)s3 * HC + cb);
                    acc[0] += w0 * t0.x; acc[1] += w0 * t0.y;
                    acc[0] += w1 * t1.x; acc[1] += w1 * t1.y;
                    acc[0] += w2 * t2.x; acc[1] += w2 * t2.y;
                    acc[0] += w3 * t3.x; acc[1] += w3 * t3.y;
                } else {
                    float t0 = hin[(size_t)s0 * HC + cb];
                    float t1 = hin[(size_t)s1 * HC + cb];
                    float t2 = hin[(size_t)s2 * HC + cb];
                    float t3 = hin[(size_t)s3 * HC + cb];
                    acc[0] += w0 * t0; acc[0] += w1 * t1; acc[0] += w2 * t2; acc[0] += w3 * t3;
                }
                if (sumth) { swacc += w0; swacc += w1; swacc += w2; swacc += w3; }
            }
            for (; j < cl; j++) {
                int s = s_src[j];
                float w = wrow[j];
                const float* hp = hin + (size_t)s * HC + cb;
                if (V == 4) {
                    float4 t = *(const float4*)hp;
                    acc[0] += w * t.x; acc[1] += w * t.y;
                    acc[2] += w * t.z; acc[3] += w * t.w;
                } else if (V == 2) {
                    float2 t = *(const float2*)hp;
                    acc[0] += w * t.x; acc[1] += w * t.y;
                } else {
                    acc[0] += w * hp[0];
                }
                if (sumth) swacc += w;
            }
        }
    }
    if (sumth) s_inv[head] = 1.f / (swacc + 1e-16f);
    __syncthreads();
    if (act) {
        float inv = s_inv[head];
#pragma unroll
        for (int v = 0; v < V; v++) {
            float val = acc[v] * inv + bias[cb + v];
            if (RELU) val = fmaxf(val, 0.f);
            if (OMODE == 0) {
                bufptr(Oid)[(size_t)n * HC + cb + v] = val;
            } else {
                halfptr(OhId)[(size_t)n * HC + cb + v] = __float2half_rn(val);
            }
        }
    }
}

// ==================== layer-3 aggregate + log_softmax (warp per node) =========
__global__ __launch_bounds__(256) void k_agg3lsm(const float* __restrict__ b3,
                                                 float* __restrict__ out) {
    int warp = threadIdx.x >> 5, lane = threadIdx.x & 31;
    int n = blockIdx.x * 8 + warp;
    if (n >= NN) return;
    int row = d_rowptr[n];
    int cnt = d_rowptr[n + 1] - row;
    float adst = d_adst[n];
    bool actc = lane < NCLS;
    float acc = 0.f, swacc = 0.f;
    int j = 0;
    for (; j + 2 <= cnt; j += 2) {
        int s0 = d_esrc[row + j], s1 = d_esrc[row + j + 1];
        float e0 = d_asrc[s0] + adst, e1 = d_asrc[s1] + adst;
        e0 = e0 > 0.f ? e0 : 0.2f * e0;
        e1 = e1 > 0.f ? e1 : 0.2f * e1;
        float w0 = __expf(e0), w1 = __expf(e1);
        float t0 = actc ? d_h3[(size_t)s0 * NCLS + lane] : 0.f;
        float t1 = actc ? d_h3[(size_t)s1 * NCLS + lane] : 0.f;
        acc += w0 * t0; acc += w1 * t1;
        swacc += w0; swacc += w1;
    }
    for (; j < cnt; j++) {
        int s = d_esrc[row + j];
        float e = d_asrc[s] + adst;
        e = e > 0.f ? e : 0.2f * e;
        float w = __expf(e);
        if (actc) acc += w * d_h3[(size_t)s * NCLS + lane];
        swacc += w;
    }
    float inv = 1.f / (swacc + 1e-16f);
    float val = actc ? (acc * inv + b3[lane]) : -1e30f;
    float m = val;
#pragma unroll
    for (int o = 8; o; o >>= 1) m = fmaxf(m, __shfl_xor_sync(0xffffffffu, m, o));
    float ex = actc ? __expf(val - m) : 0.f;
    float ssum = ex;
#pragma unroll
    for (int o = 8; o; o >>= 1) ssum += __shfl_xor_sync(0xffffffffu, ssum, o);
    if (actc) out[n * NCLS + lane] = val - (m + logf(ssum));
}

// ==================== launch ====================
extern "C" void kernel_launch(void* const* d_in, const int* in_sizes, int n_in,
                              void* d_out, int out_size) {
    const float* x   = (const float*)d_in[0];
    const int*   ei  = (const int*)d_in[1];
    const float* W1  = (const float*)d_in[2];
    const float* as1 = (const float*)d_in[3];
    const float* ad1 = (const float*)d_in[4];
    const float* b1  = (const float*)d_in[5];
    const float* W2  = (const float*)d_in[6];
    const float* as2 = (const float*)d_in[7];
    const float* ad2 = (const float*)d_in[8];
    const float* b2  = (const float*)d_in[9];
    const float* W3  = (const float*)d_in[10];
    const float* as3 = (const float*)d_in[11];
    const float* ad3 = (const float*)d_in[12];
    const float* b3  = (const float*)d_in[13];
    float* out = (float*)d_out;

    // 0-2: fp16 converts (x pass also zeroes deg/asrc/adst)
    k_half<<<(int)(((long long)NN * K1P + 255) / 256), 256>>>(x, NN, FIN, K1P, HF_XH, 1);
    k_half<<<(HC1 * K1P + 255) / 256, 256>>>(W1, HC1, FIN, K1P, HF_W1H, 0);
    k_half<<<(HC2 * HC1 + 255) / 256, 256>>>(W2, HC2, HC1, HC1, HF_W2H, 0);

    // 3: layer-1 GEMM + fused att coeffs  (ncu -s 5 captures this launch)
    {
        dim3 grid(HC1 / PN, (NN + PM - 1) / PM);
        k_mma<<<grid, 256>>>(HF_XH, HF_W1H, BUF_H1, NN, HC1, K1P, as1, ad1, 128, 8);
    }

    // 4-6: CSR build
    k_count<<<(ET + 255) / 256, 256>>>(ei);
    k_scan<<<1, 1024>>>();
    k_scatter<<<(ET + 255) / 256, 256>>>(ei);

    // 7: layer-1 aggregate -> g1 (fp16)
    k_agg<8, 128, 4, true, 1><<<NN, 256>>>(BUF_H1, b1, 0, HF_G1H);

    // 8: re-zero att accumulators for layer 2
    k_zero_att<<<(NN * 8 + 255) / 256, 256>>>();

    // 9-10: layer 2
    {
        dim3 grid(HC2 / PN, (NN + PM - 1) / PM);
        k_mma<<<grid, 256>>>(HF_G1H, HF_W2H, BUF_H2, NN, HC2, HC1, as2, ad2, 64, 8);
        k_agg<8, 64, 2, true, 0><<<NN, 256>>>(BUF_H2, b2, BUF_G2, 0);
    }
    // 11-12: layer 3 (fused agg + log_softmax)
    {
        k_gemm3<<<(NN + 7) / 8, 256>>>(W3, as3, ad3);
        k_agg3lsm<<<(NN + 7) / 8, 256>>>(b3, out);
    }
}

// round 15
// speedup vs baseline: 1.7139x; 1.0868x over previous
#include <cuda_runtime.h>
#include <cuda_fp16.h>
#include <math.h>
#include <stdint.h>

#define NN   20000
#define EE   320000
#define ET   (EE + NN)
#define FIN  745
#define K1P  768          // FIN padded to multiple of 32
#define HC1  1024         // 8 x 128
#define HC2  512          // 8 x 64
#define NCLS 10

// ==================== scratch (device globals) ====================
__device__ float d_g2[(size_t)NN * HC2];
__device__ float d_h3[(size_t)NN * NCLS];
__device__ float d_asrc[NN * 8];
__device__ float d_adst[NN * 8];
__device__ int   d_deg[NN];
__device__ int   d_rowptr[NN + 1];
__device__ int   d_cursor[NN];
__device__ int   d_esrc[ET];
// fp16 buffers
__device__ __half d_xh[(size_t)NN * K1P];
__device__ __half d_w1h[(size_t)HC1 * K1P];
__device__ __half d_w2h[(size_t)HC2 * HC1];
__device__ __half d_g1h[(size_t)NN * HC1];
__device__ __half d_h1h[(size_t)NN * HC1];
__device__ __half d_h2h[(size_t)NN * HC2];

#define BUF_G2 0
#define BUF_H3 1
__device__ __forceinline__ float* bufptr(int id) {
    switch (id) {
        case BUF_G2: return d_g2;
        default:     return d_h3;
    }
}
#define HF_XH  0
#define HF_W1H 1
#define HF_W2H 2
#define HF_G1H 3
#define HF_H1  4
#define HF_H2  5
__device__ __forceinline__ __half* halfptr(int id) {
    switch (id) {
        case HF_XH:  return d_xh;
        case HF_W1H: return d_w1h;
        case HF_W2H: return d_w2h;
        case HF_G1H: return d_g1h;
        case HF_H1:  return d_h1h;
        default:     return d_h2h;
    }
}

// ==================== CSR build ====================
__global__ void k_count(const int* __restrict__ ei) {
    int e = blockIdx.x * blockDim.x + threadIdx.x;
    if (e >= ET) return;
    int dst = (e < EE) ? ei[EE + e] : (e - EE);
    if ((unsigned)dst < (unsigned)NN) atomicAdd(&d_deg[dst], 1);
}
__global__ void k_scan() {
    __shared__ int ssum[1024];
    const int CH = (NN + 1023) / 1024;
    int t = threadIdx.x, base = t * CH, s = 0;
    for (int i = 0; i < CH; i++) { int idx = base + i; if (idx < NN) s += d_deg[idx]; }
    ssum[t] = s;
    __syncthreads();
    for (int off = 1; off < 1024; off <<= 1) {
        int v = (t >= off) ? ssum[t - off] : 0;
        __syncthreads();
        ssum[t] += v;
        __syncthreads();
    }
    int run = ssum[t] - s;
    for (int i = 0; i < CH; i++) {
        int idx = base + i;
        if (idx < NN) { d_rowptr[idx] = run; d_cursor[idx] = run; run += d_deg[idx]; }
    }
    if (t == 1023) d_rowptr[NN] = ssum[1023];
}
__global__ void k_scatter(const int* __restrict__ ei) {
    int e = blockIdx.x * blockDim.x + threadIdx.x;
    if (e >= ET) return;
    int src, dst;
    if (e < EE) { src = ei[e]; dst = ei[EE + e]; }
    else        { src = dst = e - EE; }
    if ((unsigned)dst >= (unsigned)NN || (unsigned)src >= (unsigned)NN) return;
    int pos = atomicAdd(&d_cursor[dst], 1);
    d_esrc[pos] = src;
}

// ==================== fp32 -> fp16 convert (+optional aux zeroing) ============
__global__ void k_half(const float* __restrict__ in, int rows, int Kin, int Kpad,
                       int hid, int zero_aux) {
    long long idx = (long long)blockIdx.x * blockDim.x + threadIdx.x;
    if (idx >= (long long)rows * Kpad) return;
    if (zero_aux) {
        if (idx < NN) d_deg[(int)idx] = 0;
        if (idx < NN * 8) { d_asrc[(int)idx] = 0.f; d_adst[(int)idx] = 0.f; }
    }
    int r = (int)(idx / Kpad), c = (int)(idx % Kpad);
    float v = (c < Kin) ? in[(size_t)r * Kin + c] : 0.f;
    halfptr(hid)[idx] = __float2half_rn(v);
}

__global__ void k_zero_att() {
    int i = blockIdx.x * blockDim.x + threadIdx.x;
    if (i < NN * 8) { d_asrc[i] = 0.f; d_adst[i] = 0.f; }
}

// ==================== pipelined mma.sync fp16 GEMM + fused att ================
// C[M,N] = A[M,K] @ B[N,K]^T ;  BM=128, BN=64, BK=32, 2-slot double buffer
// Output C is fp16 (halfptr(cid)). Att coeffs from fp32 accumulators.
#define PM 128
#define PN 64
#define PK 32
#define NSTAGE 2

__device__ __forceinline__ uint32_t swz64(int r, int c) {
    return (uint32_t)(r * 64 + ((c ^ ((r >> 1) & 3)) << 4));
}
__device__ __forceinline__ uint32_t smem_u32(const void* p) {
    uint32_t a;
    asm("{ .reg .u64 t; cvta.to.shared.u64 t, %1; cvt.u32.u64 %0, t; }" : "=r"(a) : "l"(p));
    return a;
}
__device__ __forceinline__ void cpa16(uint32_t s, const void* g, bool valid) {
    int sz = valid ? 16 : 0;
    asm volatile("cp.async.cg.shared.global [%0], [%1], 16, %2;" :: "r"(s), "l"(g), "r"(sz));
}
__device__ __forceinline__ void ldsm4(uint32_t* r, uint32_t addr) {
    asm volatile("ldmatrix.sync.aligned.m8n8.x4.shared.b16 {%0,%1,%2,%3}, [%4];"
        : "=r"(r[0]), "=r"(r[1]), "=r"(r[2]), "=r"(r[3]) : "r"(addr));
}
__device__ __forceinline__ void mma16816(float* d, const uint32_t* a, uint32_t b0, uint32_t b1) {
    asm volatile("mma.sync.aligned.m16n8k16.row.col.f32.f16.f16.f32 "
        "{%0,%1,%2,%3}, {%4,%5,%6,%7}, {%8,%9}, {%0,%1,%2,%3};"
        : "+f"(d[0]), "+f"(d[1]), "+f"(d[2]), "+f"(d[3])
        : "r"(a[0]), "r"(a[1]), "r"(a[2]), "r"(a[3]), "r"(b0), "r"(b1));
}

__global__ __launch_bounds__(256, 3) void k_mma(int ahid, int bhid,
                                                int cid, int M, int N, int K,
                                                const float* __restrict__ asv,
                                                const float* __restrict__ adv,
                                                int attC, int attH) {
    __shared__ __half sA[NSTAGE][PM * 32];   // 2 x 8KB
    __shared__ __half sB[NSTAGE][PN * 32];   // 2 x 4KB
    const __half* __restrict__ Ah = halfptr(ahid);
    const __half* __restrict__ Bh = halfptr(bhid);
    __half* __restrict__ Ch = halfptr(cid);

    int tid = threadIdx.x, warp = tid >> 5, lane = tid & 31;
    int wm = warp & 3, wn = warp >> 2;              // 4x2 warps, warp tile 32x32
    int row0 = blockIdx.y * PM, col0 = blockIdx.x * PN;

    int a_r = tid >> 2, a_c = tid & 3;
    int b_r = (tid >> 2) & 63, b_c = tid & 3;
    bool a_ok0 = (row0 + a_r) < M;
    bool a_ok1 = (row0 + a_r + 64) < M;
    size_t a_off0 = (size_t)(row0 + a_r) * K + a_c * 8;
    size_t a_off1 = (size_t)(row0 + a_r + 64) * K + a_c * 8;
    size_t b_off  = (size_t)(col0 + b_r) * K + b_c * 8;
    uint32_t aw0 = swz64(a_r, a_c), aw1 = swz64(a_r + 64, a_c), bw = swz64(b_r, b_c);
    uint32_t baseA[2] = { smem_u32(&sA[0][0]), smem_u32(&sA[1][0]) };
    uint32_t baseB[2] = { smem_u32(&sB[0][0]), smem_u32(&sB[1][0]) };

    float acc[2][4][4];
#pragma unroll
    for (int m = 0; m < 2; m++)
#pragma unroll
        for (int n = 0; n < 4; n++)
#pragma unroll
            for (int v = 0; v < 4; v++) acc[m][n][v] = 0.f;

    int lrow = lane & 15;
    int lck = lane >> 4;
    uint32_t offA[2][2], offB[2][2];
#pragma unroll
    for (int m = 0; m < 2; m++)
#pragma unroll
        for (int kk = 0; kk < 2; kk++) {
            offA[m][kk] = swz64(wm * 32 + m * 16 + lrow, 2 * kk + lck);
            offB[m][kk] = swz64(wn * 32 + m * 16 + lrow, 2 * kk + lck);
        }

    int nst = K / PK;
    {
        cpa16(baseA[0] + aw0, Ah + a_off0, a_ok0);
        cpa16(baseA[0] + aw1, Ah + a_off1, a_ok1);
        cpa16(baseB[0] + bw, Bh + b_off, true);
        asm volatile("cp.async.commit_group;");
    }

    for (int s = 0; s < nst; s++) {
        int slot = s & 1;
        asm volatile("cp.async.wait_group 0;");
        __syncthreads();
        if (s + 1 < nst) {
            int wr = slot ^ 1;
            int kb = (s + 1) * PK;
            cpa16(baseA[wr] + aw0, Ah + a_off0 + kb, a_ok0);
            cpa16(baseA[wr] + aw1, Ah + a_off1 + kb, a_ok1);
            cpa16(baseB[wr] + bw, Bh + b_off + kb, true);
            asm volatile("cp.async.commit_group;");
        }
#pragma unroll
        for (int kk = 0; kk < 2; kk++) {
            uint32_t ah[2][4], bh[2][4];
            ldsm4(ah[0], baseA[slot] + offA[0][kk]);
            ldsm4(ah[1], baseA[slot] + offA[1][kk]);
            ldsm4(bh[0], baseB[slot] + offB[0][kk]);
            ldsm4(bh[1], baseB[slot] + offB[1][kk]);
#pragma unroll
            for (int m = 0; m < 2; m++)
#pragma unroll
                for (int j = 0; j < 2; j++)
#pragma unroll
                    for (int hf = 0; hf < 2; hf++)
                        mma16816(acc[m][j * 2 + hf], ah[m], bh[j][hf], bh[j][hf + 2]);
        }
    }

    // epilogue: store C as fp16
#pragma unroll
    for (int m = 0; m < 2; m++) {
        int r0 = row0 + wm * 32 + m * 16 + (lane >> 2);
#pragma unroll
        for (int n8 = 0; n8 < 4; n8++) {
            int cc = col0 + wn * 32 + n8 * 8 + (lane & 3) * 2;
            if (r0 < M)
                *(__half2*)&Ch[(size_t)r0 * N + cc] =
                    __floats2half2_rn(acc[m][n8][0], acc[m][n8][1]);
            if (r0 + 8 < M)
                *(__half2*)&Ch[(size_t)(r0 + 8) * N + cc] =
                    __floats2half2_rn(acc[m][n8][2], acc[m][n8][3]);
        }
    }

    // fused attention coefficients (fp32 accs): one head per block
    if (attC) {
        int h = col0 / attC;
        int cbase = col0 % attC;
        float ps[2][2], pd[2][2];
#pragma unroll
        for (int m = 0; m < 2; m++) { ps[m][0] = ps[m][1] = pd[m][0] = pd[m][1] = 0.f; }
#pragma unroll
        for (int n8 = 0; n8 < 4; n8++) {
            int cl = cbase + wn * 32 + n8 * 8 + (lane & 3) * 2;
            float a0 = asv[h * attC + cl], a1 = asv[h * attC + cl + 1];
            float e0 = adv[h * attC + cl], e1 = adv[h * attC + cl + 1];
#pragma unroll
            for (int m = 0; m < 2; m++) {
                ps[m][0] += a0 * acc[m][n8][0] + a1 * acc[m][n8][1];
                ps[m][1] += a0 * acc[m][n8][2] + a1 * acc[m][n8][3];
                pd[m][0] += e0 * acc[m][n8][0] + e1 * acc[m][n8][1];
                pd[m][1] += e0 * acc[m][n8][2] + e1 * acc[m][n8][3];
            }
        }
#pragma unroll
        for (int off = 1; off <= 2; off <<= 1) {
#pragma unroll
            for (int m = 0; m < 2; m++) {
                ps[m][0] += __shfl_xor_sync(0xffffffffu, ps[m][0], off);
                ps[m][1] += __shfl_xor_sync(0xffffffffu, ps[m][1], off);
                pd[m][0] += __shfl_xor_sync(0xffffffffu, pd[m][0], off);
                pd[m][1] += __shfl_xor_sync(0xffffffffu, pd[m][1], off);
            }
        }
        if ((lane & 3) == 0) {
#pragma unroll
            for (int m = 0; m < 2; m++)
#pragma unroll
                for (int hf = 0; hf < 2; hf++) {
                    int r = row0 + wm * 32 + m * 16 + (lane >> 2) + hf * 8;
                    if (r < M) {
                        atomicAdd(&d_asrc[r * attH + h], ps[m][hf]);
                        atomicAdd(&d_adst[r * attH + h], pd[m][hf]);
                    }
                }
        }
    }
}

// ==================== layer-3 skinny GEMM + fused attention coeffs ====================
__global__ __launch_bounds__(256) void k_gemm3(const float* __restrict__ W3,
                                               const float* __restrict__ as3,
                                               const float* __restrict__ ad3) {
    __shared__ float sW[NCLS * HC2];
    __shared__ float sas[NCLS], sad[NCLS];
    int tid = threadIdx.x;
    for (int i = tid; i < NCLS * HC2; i += 256) sW[i] = W3[i];
    if (tid < NCLS) { sas[tid] = as3[tid]; sad[tid] = ad3[tid]; }
    __syncthreads();
    int warp = tid >> 5, lane = tid & 31;
    int r = blockIdx.x * 8 + warp;
    if (r >= NN) return;
    const float4* g = (const float4*)(d_g2 + (size_t)r * HC2);
    float pc[NCLS];
#pragma unroll
    for (int c = 0; c < NCLS; c++) pc[c] = 0.f;
#pragma unroll
    for (int i = 0; i < 4; i++) {
        float4 v = g[lane + i * 32];
        int k = (lane + i * 32) * 4;
#pragma unroll
        for (int c = 0; c < NCLS; c++) {
            float4 w = *(const float4*)&sW[c * HC2 + k];
            pc[c] += v.x * w.x + v.y * w.y + v.z * w.z + v.w * w.w;
        }
    }
    float s1 = 0.f, s2 = 0.f;
#pragma unroll
    for (int c = 0; c < NCLS; c++) {
        float t = pc[c];
#pragma unroll
        for (int o = 16; o; o >>= 1) t += __shfl_xor_sync(0xffffffffu, t, o);
        if (lane == c) d_h3[(size_t)r * NCLS + c] = t;
        s1 += t * sas[c];
        s2 += t * sad[c];
    }
    if (lane == 0) { d_asrc[r] = s1; d_adst[r] = s2; }
}

// ==================== single-pass segment softmax + aggregate (fp16 gather) ===
// hin fp16 (halfptr), fp32 accumulation. OMODE 0: fp32 out; 1: fp16 out
template <int H, int C, int V, bool RELU, int OMODE>
__global__ __launch_bounds__(256) void k_agg(int HinH, const float* __restrict__ bias,
                                             int Oid, int OhId) {
    constexpr int HC = H * C;
    const __half* __restrict__ hin = halfptr(HinH);
    int n = blockIdx.x, tid = threadIdx.x;
    int row = d_rowptr[n], cnt = d_rowptr[n + 1] - row;

    __shared__ float s_adst[H];
    __shared__ float s_w[H * 128];
    __shared__ int   s_src[128];
    __shared__ float s_inv[H];

    if (tid < H) s_adst[tid] = d_adst[n * H + tid];
    __syncthreads();

    int cb = tid * V;
    bool act = cb < HC;
    int head = act ? cb / C : 0;
    bool sumth = act && ((cb % C) == 0);
    float acc[V];
#pragma unroll
    for (int v = 0; v < V; v++) acc[v] = 0.f;
    float swacc = 0.f;

    for (int c0 = 0; c0 < cnt; c0 += 128) {
        int cl = min(128, cnt - c0);
        __syncthreads();
        if (tid < cl) {
            int s = d_esrc[row + c0 + tid];
            s_src[tid] = s;
#pragma unroll
            for (int h = 0; h < H; h++) {
                float e = d_asrc[s * H + h] + s_adst[h];
                e = e > 0.f ? e : 0.2f * e;
                s_w[h * 128 + tid] = __expf(e);
            }
        }
        __syncthreads();
        if (act) {
            const float* wrow = &s_w[head * 128];
            int j = 0;
            for (; j + 4 <= cl; j += 4) {
                int s0 = s_src[j], s1 = s_src[j + 1], s2 = s_src[j + 2], s3 = s_src[j + 3];
                float w0 = wrow[j], w1 = wrow[j + 1], w2 = wrow[j + 2], w3 = wrow[j + 3];
                if (V == 4) {
                    uint2 r0 = *(const uint2*)(hin + (size_t)s0 * HC + cb);
                    uint2 r1 = *(const uint2*)(hin + (size_t)s1 * HC + cb);
                    uint2 r2 = *(const uint2*)(hin + (size_t)s2 * HC + cb);
                    uint2 r3 = *(const uint2*)(hin + (size_t)s3 * HC + cb);
                    float2 a0 = __half22float2(*(__half2*)&r0.x), b0 = __half22float2(*(__half2*)&r0.y);
                    float2 a1 = __half22float2(*(__half2*)&r1.x), b1 = __half22float2(*(__half2*)&r1.y);
                    float2 a2 = __half22float2(*(__half2*)&r2.x), b2 = __half22float2(*(__half2*)&r2.y);
                    float2 a3 = __half22float2(*(__half2*)&r3.x), b3 = __half22float2(*(__half2*)&r3.y);
                    acc[0] += w0 * a0.x; acc[1] += w0 * a0.y; acc[2] += w0 * b0.x; acc[3] += w0 * b0.y;
                    acc[0] += w1 * a1.x; acc[1] += w1 * a1.y; acc[2] += w1 * b1.x; acc[3] += w1 * b1.y;
                    acc[0] += w2 * a2.x; acc[1] += w2 * a2.y; acc[2] += w2 * b2.x; acc[3] += w2 * b2.y;
                    acc[0] += w3 * a3.x; acc[1] += w3 * a3.y; acc[2] += w3 * b3.x; acc[3] += w3 * b3.y;
                } else if (V == 2) {
                    uint32_t r0 = *(const uint32_t*)(hin + (size_t)s0 * HC + cb);
                    uint32_t r1 = *(const uint32_t*)(hin + (size_t)s1 * HC + cb);
                    uint32_t r2 = *(const uint32_t*)(hin + (size_t)s2 * HC + cb);
                    uint32_t r3 = *(const uint32_t*)(hin + (size_t)s3 * HC + cb);
                    float2 a0 = __half22float2(*(__half2*)&r0);
                    float2 a1 = __half22float2(*(__half2*)&r1);
                    float2 a2 = __half22float2(*(__half2*)&r2);
                    float2 a3 = __half22float2(*(__half2*)&r3);
                    acc[0] += w0 * a0.x; acc[1] += w0 * a0.y;
                    acc[0] += w1 * a1.x; acc[1] += w1 * a1.y;
                    acc[0] += w2 * a2.x; acc[1] += w2 * a2.y;
                    acc[0] += w3 * a3.x; acc[1] += w3 * a3.y;
                }
                if (sumth) { swacc += w0; swacc += w1; swacc += w2; swacc += w3; }
            }
            for (; j < cl; j++) {
                int s = s_src[j];
                float w = wrow[j];
                const __half* hp = hin + (size_t)s * HC + cb;
                if (V == 4) {
                    uint2 r = *(const uint2*)hp;
                    float2 a = __half22float2(*(__half2*)&r.x), b = __half22float2(*(__half2*)&r.y);
                    acc[0] += w * a.x; acc[1] += w * a.y; acc[2] += w * b.x; acc[3] += w * b.y;
                } else if (V == 2) {
                    uint32_t r = *(const uint32_t*)hp;
                    float2 a = __half22float2(*(__half2*)&r);
                    acc[0] += w * a.x; acc[1] += w * a.y;
                }
                if (sumth) swacc += w;
            }
        }
    }
    if (sumth) s_inv[head] = 1.f / (swacc + 1e-16f);
    __syncthreads();
    if (act) {
        float inv = s_inv[head];
#pragma unroll
        for (int v = 0; v < V; v++) {
            float val = acc[v] * inv + bias[cb + v];
            if (RELU) val = fmaxf(val, 0.f);
            if (OMODE == 0) {
                bufptr(Oid)[(size_t)n * HC + cb + v] = val;
            } else {
                halfptr(OhId)[(size_t)n * HC + cb + v] = __float2half_rn(val);
            }
        }
    }
}

// ==================== layer-3 aggregate + log_softmax (warp per node) =========
__global__ __launch_bounds__(256) void k_agg3lsm(const float* __restrict__ b3,
                                                 float* __restrict__ out) {
    int warp = threadIdx.x >> 5, lane = threadIdx.x & 31;
    int n = blockIdx.x * 8 + warp;
    if (n >= NN) return;
    int row = d_rowptr[n];
    int cnt = d_rowptr[n + 1] - row;
    float adst = d_adst[n];
    bool actc = lane < NCLS;
    float acc = 0.f, swacc = 0.f;
    int j = 0;
    for (; j + 2 <= cnt; j += 2) {
        int s0 = d_esrc[row + j], s1 = d_esrc[row + j + 1];
        float e0 = d_asrc[s0] + adst, e1 = d_asrc[s1] + adst;
        e0 = e0 > 0.f ? e0 : 0.2f * e0;
        e1 = e1 > 0.f ? e1 : 0.2f * e1;
        float w0 = __expf(e0), w1 = __expf(e1);
        float t0 = actc ? d_h3[(size_t)s0 * NCLS + lane] : 0.f;
        float t1 = actc ? d_h3[(size_t)s1 * NCLS + lane] : 0.f;
        acc += w0 * t0; acc += w1 * t1;
        swacc += w0; swacc += w1;
    }
    for (; j < cnt; j++) {
        int s = d_esrc[row + j];
        float e = d_asrc[s] + adst;
        e = e > 0.f ? e : 0.2f * e;
        float w = __expf(e);
        if (actc) acc += w * d_h3[(size_t)s * NCLS + lane];
        swacc += w;
    }
    float inv = 1.f / (swacc + 1e-16f);
    float val = actc ? (acc * inv + b3[lane]) : -1e30f;
    float m = val;
#pragma unroll
    for (int o = 8; o; o >>= 1) m = fmaxf(m, __shfl_xor_sync(0xffffffffu, m, o));
    float ex = actc ? __expf(val - m) : 0.f;
    float ssum = ex;
#pragma unroll
    for (int o = 8; o; o >>= 1) ssum += __shfl_xor_sync(0xffffffffu, ssum, o);
    if (actc) out[n * NCLS + lane] = val - (m + logf(ssum));
}

// ==================== launch ====================
extern "C" void kernel_launch(void* const* d_in, const int* in_sizes, int n_in,
                              void* d_out, int out_size) {
    const float* x   = (const float*)d_in[0];
    const int*   ei  = (const int*)d_in[1];
    const float* W1  = (const float*)d_in[2];
    const float* as1 = (const float*)d_in[3];
    const float* ad1 = (const float*)d_in[4];
    const float* b1  = (const float*)d_in[5];
    const float* W2  = (const float*)d_in[6];
    const float* as2 = (const float*)d_in[7];
    const float* ad2 = (const float*)d_in[8];
    const float* b2  = (const float*)d_in[9];
    const float* W3  = (const float*)d_in[10];
    const float* as3 = (const float*)d_in[11];
    const float* ad3 = (const float*)d_in[12];
    const float* b3  = (const float*)d_in[13];
    float* out = (float*)d_out;

    // 0-2: fp16 converts (x pass also zeroes deg/asrc/adst)
    k_half<<<(int)(((long long)NN * K1P + 255) / 256), 256>>>(x, NN, FIN, K1P, HF_XH, 1);
    k_half<<<(HC1 * K1P + 255) / 256, 256>>>(W1, HC1, FIN, K1P, HF_W1H, 0);
    k_half<<<(HC2 * HC1 + 255) / 256, 256>>>(W2, HC2, HC1, HC1, HF_W2H, 0);

    // 3: layer-1 GEMM (fp16 out) + fused att coeffs
    {
        dim3 grid(HC1 / PN, (NN + PM - 1) / PM);
        k_mma<<<grid, 256>>>(HF_XH, HF_W1H, HF_H1, NN, HC1, K1P, as1, ad1, 128, 8);
    }

    // 4-6: CSR build
    k_count<<<(ET + 255) / 256, 256>>>(ei);
    k_scan<<<1, 1024>>>();
    k_scatter<<<(ET + 255) / 256, 256>>>(ei);

    // 7: layer-1 aggregate (fp16 gather) -> g1 fp16
    k_agg<8, 128, 4, true, 1><<<NN, 256>>>(HF_H1, b1, 0, HF_G1H);

    // 8: re-zero att accumulators for layer 2
    k_zero_att<<<(NN * 8 + 255) / 256, 256>>>();

    // 9-10: layer 2
    {
        dim3 grid(HC2 / PN, (NN + PM - 1) / PM);
        k_mma<<<grid, 256>>>(HF_G1H, HF_W2H, HF_H2, NN, HC2, HC1, as2, ad2, 64, 8);
        k_agg<8, 64, 2, true, 0><<<NN, 256>>>(HF_H2, b2, BUF_G2, 0);
    }
    // 11-12: layer 3 (fused agg + log_softmax)
    {
        k_gemm3<<<(NN + 7) / 8, 256>>>(W3, as3, ad3);
        k_agg3lsm<<<(NN + 7) / 8, 256>>>(b3, out);
    }
}